// round 3
// baseline (speedup 1.0000x reference)
#include <cuda_runtime.h>
#include <cuda_bf16.h>
#include <cstdint>

#define NUM_PINS_MAX   2000000
#define MAX_BLOCKS     4096

// Scratch: packed (x,y) per pin, per-block partial sums, completion counter.
__device__ float2       g_pinxy[NUM_PINS_MAX];
__device__ double       g_partials[MAX_BLOCKS];
__device__ unsigned int g_counter = 0;

// ---------------------------------------------------------------------------
// Kernel A: pack x/y halves of pin_pos into float2 array, 4 pins per thread.
// NOTE: g_pinxy address taken in DEVICE code (host-side symbol ref is UB and
// on GB300 silently writes host shadow memory via ATS).
// ---------------------------------------------------------------------------
__global__ void __launch_bounds__(256)
pack_pins_kernel(const float4* __restrict__ x4,
                 const float4* __restrict__ y4,
                 int n4)                      // n_pins / 4
{
    float4* __restrict__ out4 = reinterpret_cast<float4*>(g_pinxy);
    int i = blockIdx.x * blockDim.x + threadIdx.x;
    if (i < n4) {
        float4 x = x4[i];
        float4 y = y4[i];
        float4 lo = make_float4(x.x, y.x, x.y, y.y);
        float4 hi = make_float4(x.z, y.z, x.w, y.w);
        out4[2 * i]     = lo;
        out4[2 * i + 1] = hi;
    }
}

// ---------------------------------------------------------------------------
// Kernel B: main pair loop, 4 pairs per iteration (2x int4 + 1x float4),
// with last-block final reduction (threadfence + atomic counter).
// ---------------------------------------------------------------------------
__global__ void __launch_bounds__(256)
pair_attraction_kernel(const int4*   __restrict__ pairs4,   // [n_pairs/2]
                       const float4* __restrict__ w4,       // [n_pairs/4]
                       int n_oct,                           // n_pairs / 4
                       float* __restrict__ out)
{
    const float2* __restrict__ pinxy = g_pinxy;

    float acc0 = 0.0f, acc1 = 0.0f, acc2 = 0.0f, acc3 = 0.0f;
    int stride = gridDim.x * blockDim.x;

    for (int i = blockIdx.x * blockDim.x + threadIdx.x; i < n_oct; i += stride) {
        // streaming loads (evict-first): keep L2 for the pin gather set
        int4   pA = __ldcs(&pairs4[2 * i]);
        int4   pB = __ldcs(&pairs4[2 * i + 1]);
        float4 w  = __ldcs(&w4[i]);

        float2 a0 = __ldg(&pinxy[pA.x]);
        float2 b0 = __ldg(&pinxy[pA.y]);
        float2 a1 = __ldg(&pinxy[pA.z]);
        float2 b1 = __ldg(&pinxy[pA.w]);
        float2 a2 = __ldg(&pinxy[pB.x]);
        float2 b2 = __ldg(&pinxy[pB.y]);
        float2 a3 = __ldg(&pinxy[pB.z]);
        float2 b3 = __ldg(&pinxy[pB.w]);

        float dx0 = a0.x - b0.x, dy0 = a0.y - b0.y;
        float dx1 = a1.x - b1.x, dy1 = a1.y - b1.y;
        float dx2 = a2.x - b2.x, dy2 = a2.y - b2.y;
        float dx3 = a3.x - b3.x, dy3 = a3.y - b3.y;

        acc0 = fmaf(w.x, fmaf(dx0, dx0, dy0 * dy0), acc0);
        acc1 = fmaf(w.y, fmaf(dx1, dx1, dy1 * dy1), acc1);
        acc2 = fmaf(w.z, fmaf(dx2, dx2, dy2 * dy2), acc2);
        acc3 = fmaf(w.w, fmaf(dx3, dx3, dy3 * dy3), acc3);
    }

    float acc = (acc0 + acc1) + (acc2 + acc3);

    // warp reduce (fp32)
    #pragma unroll
    for (int off = 16; off > 0; off >>= 1)
        acc += __shfl_xor_sync(0xFFFFFFFFu, acc, off);

    // block reduce via shared (double for cross-warp combine)
    __shared__ double warp_sums[8];   // 256 threads = 8 warps
    int lane = threadIdx.x & 31;
    int wid  = threadIdx.x >> 5;
    if (lane == 0) warp_sums[wid] = (double)acc;
    __syncthreads();

    if (wid == 0) {
        double v = (lane < 8) ? warp_sums[lane] : 0.0;
        #pragma unroll
        for (int off = 4; off > 0; off >>= 1)
            v += __shfl_xor_sync(0xFFFFFFFFu, v, off);
        if (lane == 0) g_partials[blockIdx.x] = v;
    }

    // ---- last-block final reduction ----
    __shared__ bool is_last;
    if (threadIdx.x == 0) {
        __threadfence();  // make this block's partial visible
        unsigned int old = atomicAdd(&g_counter, 1u);
        is_last = (old == gridDim.x - 1);
    }
    __syncthreads();

    if (is_last) {
        __threadfence();  // acquire: see all other blocks' partials
        double v = 0.0;
        for (int i = threadIdx.x; i < (int)gridDim.x; i += blockDim.x)
            v += g_partials[i];

        #pragma unroll
        for (int off = 16; off > 0; off >>= 1)
            v += __shfl_xor_sync(0xFFFFFFFFu, v, off);

        __shared__ double fin[8];
        if (lane == 0) fin[wid] = v;
        __syncthreads();

        if (wid == 0) {
            double s = (lane < 8) ? fin[lane] : 0.0;
            #pragma unroll
            for (int off = 4; off > 0; off >>= 1)
                s += __shfl_xor_sync(0xFFFFFFFFu, s, off);
            if (lane == 0) {
                out[0] = (float)s;
                g_counter = 0;   // reset for next graph replay (deterministic)
            }
        }
    }
}

// ---------------------------------------------------------------------------
// Launcher
// ---------------------------------------------------------------------------
extern "C" void kernel_launch(void* const* d_in, const int* in_sizes, int n_in,
                              void* d_out, int out_size) {
    const float* pin_pos = (const float*)d_in[0];
    const float* weights = (const float*)d_in[1];
    const int*   pairs   = (const int*)d_in[2];
    // d_in[3] = pin_mask (unused by the reference computation)

    int n_pins  = in_sizes[0] / 2;          // 2,000,000
    int n_pairs = in_sizes[2] / 2;          // 10,000,000
    int n_oct   = n_pairs / 4;              // 2,500,000

    float* out = (float*)d_out;

    // A: pack pins (vectorized, 4 pins/thread, symbol resolved in device code)
    {
        int n4      = n_pins / 4;           // 500,000 (n_pins % 4 == 0)
        int threads = 256;
        int blocks  = (n4 + threads - 1) / threads;
        pack_pins_kernel<<<blocks, threads>>>(
            (const float4*)pin_pos,
            (const float4*)(pin_pos + n_pins),
            n4);
    }

    // B: main loop + fused final reduction
    int threads = 256;
    int blocks  = 148 * 8;                  // 1184 blocks
    if (blocks > MAX_BLOCKS) blocks = MAX_BLOCKS;
    pair_attraction_kernel<<<blocks, threads>>>(
        (const int4*)pairs, (const float4*)weights, n_oct, out);
}

// round 4
// speedup vs baseline: 1.0489x; 1.0489x over previous
#include <cuda_runtime.h>
#include <cuda_bf16.h>
#include <cstdint>

#define NUM_PINS_MAX   2000000
#define MAX_BLOCKS     4096

// Scratch: packed (x,y) per pin, per-block partial sums, completion counter.
__device__ float2       g_pinxy[NUM_PINS_MAX];
__device__ double       g_partials[MAX_BLOCKS];
__device__ unsigned int g_counter = 0;

// ---------------------------------------------------------------------------
// Kernel A: pack x/y halves of pin_pos into float2 array, 4 pins per thread.
// g_pinxy address taken in DEVICE code only (host-side __device__ symbol ref
// silently hits ATS host shadow memory on GB300).
// ---------------------------------------------------------------------------
__global__ void __launch_bounds__(256)
pack_pins_kernel(const float4* __restrict__ x4,
                 const float4* __restrict__ y4,
                 int n4)                      // n_pins / 4
{
    float4* __restrict__ out4 = reinterpret_cast<float4*>(g_pinxy);
    int i = blockIdx.x * blockDim.x + threadIdx.x;
    if (i < n4) {
        float4 x = x4[i];
        float4 y = y4[i];
        out4[2 * i]     = make_float4(x.x, y.x, x.y, y.y);
        out4[2 * i + 1] = make_float4(x.z, y.z, x.w, y.w);
    }
}

// ---------------------------------------------------------------------------
// Kernel B: main pair loop. Two COALESCED quad streams (each thread handles
// quad j and quad j + n_half, both warp-contiguous) -> 4 pairs/iter with
// perfect streaming coalescing + 8 gathers in flight.
// Fused last-block final reduction.
// ---------------------------------------------------------------------------
__global__ void __launch_bounds__(256)
pair_attraction_kernel(const int4*   __restrict__ pairs4,   // [n_quads] (a0,b0,a1,b1)
                       const float2* __restrict__ w2,       // [n_quads]
                       int n_half,                          // n_quads / 2
                       float* __restrict__ out)
{
    const float2* __restrict__ pinxy = g_pinxy;

    float acc0 = 0.0f, acc1 = 0.0f, acc2 = 0.0f, acc3 = 0.0f;
    int stride = gridDim.x * blockDim.x;

    for (int j = blockIdx.x * blockDim.x + threadIdx.x; j < n_half; j += stride) {
        int j2 = j + n_half;

        // streaming loads, evict-first, fully coalesced within each warp
        int4   pA = __ldcs(&pairs4[j]);
        int4   pB = __ldcs(&pairs4[j2]);
        float2 wA = __ldcs(&w2[j]);
        float2 wB = __ldcs(&w2[j2]);

        float2 a0 = __ldg(&pinxy[pA.x]);
        float2 b0 = __ldg(&pinxy[pA.y]);
        float2 a1 = __ldg(&pinxy[pA.z]);
        float2 b1 = __ldg(&pinxy[pA.w]);
        float2 a2 = __ldg(&pinxy[pB.x]);
        float2 b2 = __ldg(&pinxy[pB.y]);
        float2 a3 = __ldg(&pinxy[pB.z]);
        float2 b3 = __ldg(&pinxy[pB.w]);

        float dx0 = a0.x - b0.x, dy0 = a0.y - b0.y;
        float dx1 = a1.x - b1.x, dy1 = a1.y - b1.y;
        float dx2 = a2.x - b2.x, dy2 = a2.y - b2.y;
        float dx3 = a3.x - b3.x, dy3 = a3.y - b3.y;

        acc0 = fmaf(wA.x, fmaf(dx0, dx0, dy0 * dy0), acc0);
        acc1 = fmaf(wA.y, fmaf(dx1, dx1, dy1 * dy1), acc1);
        acc2 = fmaf(wB.x, fmaf(dx2, dx2, dy2 * dy2), acc2);
        acc3 = fmaf(wB.y, fmaf(dx3, dx3, dy3 * dy3), acc3);
    }

    float acc = (acc0 + acc1) + (acc2 + acc3);

    // warp reduce (fp32)
    #pragma unroll
    for (int off = 16; off > 0; off >>= 1)
        acc += __shfl_xor_sync(0xFFFFFFFFu, acc, off);

    // block reduce via shared (double for cross-warp combine)
    __shared__ double warp_sums[8];   // 256 threads = 8 warps
    int lane = threadIdx.x & 31;
    int wid  = threadIdx.x >> 5;
    if (lane == 0) warp_sums[wid] = (double)acc;
    __syncthreads();

    if (wid == 0) {
        double v = (lane < 8) ? warp_sums[lane] : 0.0;
        #pragma unroll
        for (int off = 4; off > 0; off >>= 1)
            v += __shfl_xor_sync(0xFFFFFFFFu, v, off);
        if (lane == 0) g_partials[blockIdx.x] = v;
    }

    // ---- last-block final reduction ----
    __shared__ bool is_last;
    if (threadIdx.x == 0) {
        __threadfence();  // make this block's partial visible
        unsigned int old = atomicAdd(&g_counter, 1u);
        is_last = (old == gridDim.x - 1);
    }
    __syncthreads();

    if (is_last) {
        __threadfence();  // acquire: see all other blocks' partials
        double v = 0.0;
        for (int i = threadIdx.x; i < (int)gridDim.x; i += blockDim.x)
            v += g_partials[i];

        #pragma unroll
        for (int off = 16; off > 0; off >>= 1)
            v += __shfl_xor_sync(0xFFFFFFFFu, v, off);

        __shared__ double fin[8];
        if (lane == 0) fin[wid] = v;
        __syncthreads();

        if (wid == 0) {
            double s = (lane < 8) ? fin[lane] : 0.0;
            #pragma unroll
            for (int off = 4; off > 0; off >>= 1)
                s += __shfl_xor_sync(0xFFFFFFFFu, s, off);
            if (lane == 0) {
                out[0] = (float)s;
                g_counter = 0;   // reset for next graph replay (deterministic)
            }
        }
    }
}

// ---------------------------------------------------------------------------
// Launcher
// ---------------------------------------------------------------------------
extern "C" void kernel_launch(void* const* d_in, const int* in_sizes, int n_in,
                              void* d_out, int out_size) {
    const float* pin_pos = (const float*)d_in[0];
    const float* weights = (const float*)d_in[1];
    const int*   pairs   = (const int*)d_in[2];
    // d_in[3] = pin_mask (unused by the reference computation)

    int n_pins  = in_sizes[0] / 2;          // 2,000,000
    int n_pairs = in_sizes[2] / 2;          // 10,000,000
    int n_quads = n_pairs / 2;              // 5,000,000
    int n_half  = n_quads / 2;              // 2,500,000

    float* out = (float*)d_out;

    // A: pack pins (vectorized, 4 pins/thread)
    {
        int n4      = n_pins / 4;           // 500,000
        int threads = 256;
        int blocks  = (n4 + threads - 1) / threads;
        pack_pins_kernel<<<blocks, threads>>>(
            (const float4*)pin_pos,
            (const float4*)(pin_pos + n_pins),
            n4);
    }

    // B: main loop + fused final reduction
    int threads = 256;
    int blocks  = 148 * 8;                  // 1184 blocks
    if (blocks > MAX_BLOCKS) blocks = MAX_BLOCKS;
    pair_attraction_kernel<<<blocks, threads>>>(
        (const int4*)pairs, (const float2*)weights, n_half, out);
}

// round 5
// speedup vs baseline: 1.0643x; 1.0147x over previous
#include <cuda_runtime.h>
#include <cuda_bf16.h>
#include <cstdint>

#define NUM_PINS_MAX   2000000
#define MAX_BLOCKS     4096

// Scratch: packed (x,y) per pin, per-block partial sums, completion counter.
__device__ float2       g_pinxy[NUM_PINS_MAX];
__device__ double       g_partials[MAX_BLOCKS];
__device__ unsigned int g_counter = 0;

// ---------------------------------------------------------------------------
// Kernel A: pack x/y halves of pin_pos into float2 array, 4 pins per thread.
// g_pinxy address taken in DEVICE code only (host-side __device__ symbol ref
// silently hits ATS host shadow memory on GB300).
// ---------------------------------------------------------------------------
__global__ void __launch_bounds__(256)
pack_pins_kernel(const float4* __restrict__ x4,
                 const float4* __restrict__ y4,
                 int n4)                      // n_pins / 4
{
    float4* __restrict__ out4 = reinterpret_cast<float4*>(g_pinxy);
    int i = blockIdx.x * blockDim.x + threadIdx.x;
    if (i < n4) {
        float4 x = x4[i];
        float4 y = y4[i];
        out4[2 * i]     = make_float4(x.x, y.x, x.y, y.y);
        out4[2 * i + 1] = make_float4(x.z, y.z, x.w, y.w);
    }
}

// ---------------------------------------------------------------------------
// Kernel B: main pair loop — ONE quad per iteration (4 gathers in flight).
// MLP_p1 kept at ~6 to stay below the L1tex cross-CTA queue-contention knee
// (B300: MLP_p1=12 -> 2.0x CTA spread, MLP_p1=4 -> 1.3x).
// Fused last-block final reduction.
// ---------------------------------------------------------------------------
__global__ void __launch_bounds__(256)
pair_attraction_kernel(const int4*   __restrict__ pairs4,   // [n_quads] (a0,b0,a1,b1)
                       const float2* __restrict__ w2,       // [n_quads]
                       int n_quads,
                       float* __restrict__ out)
{
    const float2* __restrict__ pinxy = g_pinxy;

    float acc0 = 0.0f, acc1 = 0.0f;
    int stride = gridDim.x * blockDim.x;

    for (int i = blockIdx.x * blockDim.x + threadIdx.x; i < n_quads; i += stride) {
        // streaming loads, evict-first, fully coalesced within each warp
        int4   p = __ldcs(&pairs4[i]);
        float2 w = __ldcs(&w2[i]);

        float2 a0 = __ldg(&pinxy[p.x]);
        float2 b0 = __ldg(&pinxy[p.y]);
        float2 a1 = __ldg(&pinxy[p.z]);
        float2 b1 = __ldg(&pinxy[p.w]);

        float dx0 = a0.x - b0.x, dy0 = a0.y - b0.y;
        float dx1 = a1.x - b1.x, dy1 = a1.y - b1.y;

        acc0 = fmaf(w.x, fmaf(dx0, dx0, dy0 * dy0), acc0);
        acc1 = fmaf(w.y, fmaf(dx1, dx1, dy1 * dy1), acc1);
    }

    float acc = acc0 + acc1;

    // warp reduce (fp32)
    #pragma unroll
    for (int off = 16; off > 0; off >>= 1)
        acc += __shfl_xor_sync(0xFFFFFFFFu, acc, off);

    // block reduce via shared (double for cross-warp combine)
    __shared__ double warp_sums[8];   // 256 threads = 8 warps
    int lane = threadIdx.x & 31;
    int wid  = threadIdx.x >> 5;
    if (lane == 0) warp_sums[wid] = (double)acc;
    __syncthreads();

    if (wid == 0) {
        double v = (lane < 8) ? warp_sums[lane] : 0.0;
        #pragma unroll
        for (int off = 4; off > 0; off >>= 1)
            v += __shfl_xor_sync(0xFFFFFFFFu, v, off);
        if (lane == 0) g_partials[blockIdx.x] = v;
    }

    // ---- last-block final reduction ----
    __shared__ bool is_last;
    if (threadIdx.x == 0) {
        __threadfence();  // make this block's partial visible
        unsigned int old = atomicAdd(&g_counter, 1u);
        is_last = (old == gridDim.x - 1);
    }
    __syncthreads();

    if (is_last) {
        __threadfence();  // acquire: see all other blocks' partials
        double v = 0.0;
        for (int i = threadIdx.x; i < (int)gridDim.x; i += blockDim.x)
            v += g_partials[i];

        #pragma unroll
        for (int off = 16; off > 0; off >>= 1)
            v += __shfl_xor_sync(0xFFFFFFFFu, v, off);

        __shared__ double fin[8];
        if (lane == 0) fin[wid] = v;
        __syncthreads();

        if (wid == 0) {
            double s = (lane < 8) ? fin[lane] : 0.0;
            #pragma unroll
            for (int off = 4; off > 0; off >>= 1)
                s += __shfl_xor_sync(0xFFFFFFFFu, s, off);
            if (lane == 0) {
                out[0] = (float)s;
                g_counter = 0;   // reset for next graph replay (deterministic)
            }
        }
    }
}

// ---------------------------------------------------------------------------
// Launcher
// ---------------------------------------------------------------------------
extern "C" void kernel_launch(void* const* d_in, const int* in_sizes, int n_in,
                              void* d_out, int out_size) {
    const float* pin_pos = (const float*)d_in[0];
    const float* weights = (const float*)d_in[1];
    const int*   pairs   = (const int*)d_in[2];
    // d_in[3] = pin_mask (unused by the reference computation)

    int n_pins  = in_sizes[0] / 2;          // 2,000,000
    int n_pairs = in_sizes[2] / 2;          // 10,000,000
    int n_quads = n_pairs / 2;              // 5,000,000

    float* out = (float*)d_out;

    // A: pack pins (vectorized, 4 pins/thread)
    {
        int n4      = n_pins / 4;           // 500,000
        int threads = 256;
        int blocks  = (n4 + threads - 1) / threads;
        pack_pins_kernel<<<blocks, threads>>>(
            (const float4*)pin_pos,
            (const float4*)(pin_pos + n_pins),
            n4);
    }

    // B: main loop + fused final reduction
    int threads = 256;
    int blocks  = 148 * 8;                  // 1184 blocks = one full wave
    if (blocks > MAX_BLOCKS) blocks = MAX_BLOCKS;
    pair_attraction_kernel<<<blocks, threads>>>(
        (const int4*)pairs, (const float2*)weights, n_quads, out);
}